// round 14
// baseline (speedup 1.0000x reference)
#include <cuda_runtime.h>
#include <cuda_fp16.h>
#include <cstdint>
#include <cstddef>

#define Bc 2
#define Sc 4096
#define Cc 2048
#define Hc 16
#define Dc 128
#define NSPLIT 8

// ---------------- scratch (device globals; no allocation) ----------------
__device__ float g_VKpart[NSPLIT][(size_t)Bc * Hc * 129 * Dc];
__device__ __half g_Qh[(size_t)Bc * Hc * Sc * Dc];   // fp16 (b,h,s,d)
__device__ __half g_Kh[(size_t)Bc * Hc * Sc * Dc];
__device__ __half g_Vh[(size_t)Bc * Hc * Sc * Dc];
__device__ __half g_VKh[(size_t)Bc * Hc * 129 * Dc]; // fp16
// K-major tiled+swizzled operands
__device__ __half g_XT[(size_t)32 * 2048 * 256];     // x^T  [mblk][k][mi]
__device__ __half g_WT[(size_t)64 * 2048 * 128];     // qkv|o [nblk][k][ni]
__device__ __half g_ATT_T[(size_t)32 * 2048 * 256];  // attn out, same as XT

// ======================= helpers =======================
__device__ __forceinline__ uint32_t smem_u32(const void* p) {
    return (uint32_t)__cvta_generic_to_shared(p);
}
__device__ __forceinline__ uint32_t pack_h2(float x, float y) {
    __half2 h = __floats2half2_rn(x, y);
    return *reinterpret_cast<uint32_t*>(&h);
}
__device__ __forceinline__ void mbar_init(uint32_t a, uint32_t cnt) {
    asm volatile("mbarrier.init.shared.b64 [%0], %1;" :: "r"(a), "r"(cnt) : "memory");
}
__device__ __forceinline__ void mbar_expect_tx(uint32_t a, uint32_t bytes) {
    asm volatile("mbarrier.arrive.expect_tx.shared.b64 _, [%0], %1;"
                 :: "r"(a), "r"(bytes) : "memory");
}
__device__ __forceinline__ void mbar_wait(uint32_t a, uint32_t parity) {
    uint32_t done = 0;
    while (!done) {
        asm volatile(
            "{\n\t.reg .pred p;\n\t"
            "mbarrier.try_wait.parity.acquire.cta.shared::cta.b64 p, [%1], %2, 0x989680;\n\t"
            "selp.b32 %0, 1, 0, p;\n\t}"
            : "=r"(done) : "r"(a), "r"(parity) : "memory");
    }
}
__device__ __forceinline__ void bulk_g2s(uint32_t dst, const void* src,
                                         uint32_t bytes, uint32_t mbar) {
    asm volatile(
        "cp.async.bulk.shared::cluster.global.mbarrier::complete_tx::bytes "
        "[%0], [%1], %2, [%3];"
        :: "r"(dst), "l"(__cvta_generic_to_global(src)), "r"(bytes), "r"(mbar)
        : "memory");
}

#define LDSM_X4(r, addr) \
    asm volatile("ldmatrix.sync.aligned.m8n8.x4.shared.b16 {%0,%1,%2,%3}, [%4];" \
        : "=r"((r)[0]), "=r"((r)[1]), "=r"((r)[2]), "=r"((r)[3]) : "r"(addr))
#define LDSM_X4_T(r, addr) \
    asm volatile("ldmatrix.sync.aligned.m8n8.x4.trans.shared.b16 {%0,%1,%2,%3}, [%4];" \
        : "=r"((r)[0]), "=r"((r)[1]), "=r"((r)[2]), "=r"((r)[3]) : "r"(addr))
#define MMA_F16(d, a0, a1, a2, a3, b0, b1) \
    asm volatile("mma.sync.aligned.m16n8k16.row.col.f32.f16.f16.f32 " \
        "{%0,%1,%2,%3}, {%4,%5,%6,%7}, {%8,%9}, {%0,%1,%2,%3};" \
        : "+f"((d)[0]), "+f"((d)[1]), "+f"((d)[2]), "+f"((d)[3]) \
        : "r"(a0), "r"(a1), "r"(a2), "r"(a3), "r"(b0), "r"(b1))

// ======================= fp32 -> fp16 K-major tiled+swizzled transpose ======
__device__ __forceinline__ void convert_tile(const float* __restrict__ src,
                                             __half* __restrict__ dst,
                                             int k0, int m0, int blkShift, int tid)
{
    __shared__ __half ts[64][72];

    for (int idx = tid; idx < 64 * 32; idx += 256) {
        const int ml = idx >> 5, kp = idx & 31;
        const float2 f = *(const float2*)(src + (size_t)(m0 + ml) * 2048 + k0 + kp * 2);
        *(uint32_t*)&ts[ml][kp * 2] = pack_h2(f.x, f.y);
    }
    __syncthreads();

    const int blkM = 1 << blkShift;
    const int mblk = m0 >> blkShift;
    const int b0 = (m0 & (blkM - 1)) >> 3;
    const size_t blkElems = (size_t)2048 << blkShift;

    for (int ci = tid; ci < 512; ci += 256) {
        const int kl = ci >> 3, p = ci & 7;
        const int k = k0 + kl;
        const int cl = p ^ (k & 7);
        __half v[8];
#pragma unroll
        for (int j = 0; j < 8; j++) v[j] = ts[cl * 8 + j][kl];
        __half* o = dst + (size_t)mblk * blkElems + (size_t)k * blkM + (b0 + p) * 8;
        *(uint4*)o = *(uint4*)v;
    }
}

__global__ void convert_x(const float* __restrict__ src, __half* __restrict__ dst)
{
    convert_tile(src, dst, blockIdx.x * 64, blockIdx.y * 64, 8, threadIdx.x);
}
__global__ void convert_w(const float* __restrict__ w0, const float* __restrict__ w1,
                          const float* __restrict__ w2, const float* __restrict__ w3,
                          __half* __restrict__ dst)
{
    const float* w = (blockIdx.z == 0) ? w0 : (blockIdx.z == 1) ? w1
                   : (blockIdx.z == 2) ? w2 : w3;
    convert_tile(w, dst + (size_t)blockIdx.z * (16 * 262144),
                 blockIdx.x * 64, blockIdx.y * 64, 7, threadIdx.x);
}

// ======================= fp16 HMMA GEMM, 4-stage bulk pipeline ==============
// CTA 256x128, K-chunk 64, 4 stages (48KB each), 16 warps (8M x 2N), warp 32x64.
// SMEM stage: A [64 k][256 m] = 32KB | B [64 k][128 n] = 16KB (pre-swizzled).
#define KCH 64
#define NCHUNK (Cc / KCH)          // 32
#define OFFB 32768
#define STAGEB 49152
#define TXBYTES 49152
#define NSTG 4
#define NT 512

template <int QKV>
__global__ void __launch_bounds__(NT, 1) mma_gemm(
    const __half* __restrict__ Ah, const __half* __restrict__ Bh,
    const float* __restrict__ b0p, const float* __restrict__ b1p,
    const float* __restrict__ b2p,
    const float* __restrict__ cosT, const float* __restrict__ sinT,
    float* __restrict__ dout)
{
    extern __shared__ __align__(16) char dyn[];
    __shared__ __align__(8) uint64_t mbar_store[NSTG];

    const int tid = threadIdx.x;
    const int lane = tid & 31;
    const int wid = tid >> 5;
    const int m0 = blockIdx.y * 256;
    const int n0 = blockIdx.x * 128;
    const int warp_m = (wid >> 1) * 32;
    const int warp_n = (wid & 1) * 64;

    const uint32_t sb = smem_u32(dyn);
    uint32_t mb[NSTG];
#pragma unroll
    for (int s = 0; s < NSTG; s++) mb[s] = smem_u32(&mbar_store[s]);

    if (tid == 0) {
#pragma unroll
        for (int s = 0; s < NSTG; s++) mbar_init(mb[s], 1);
    }
    __syncthreads();

    const __half* aBase = Ah + (size_t)blockIdx.y * (2048 * 256);
    const __half* bBase = Bh + (size_t)blockIdx.x * (2048 * 128);

    auto load_chunk = [&](int kt) {
        if (tid == 0) {
            const int s = kt & (NSTG - 1);
            const uint32_t st = sb + (uint32_t)s * STAGEB;
            mbar_expect_tx(mb[s], TXBYTES);
            bulk_g2s(st, aBase + (size_t)kt * (KCH * 256), 32768, mb[s]);
            bulk_g2s(st + OFFB, bBase + (size_t)kt * (KCH * 128), 16384, mb[s]);
        }
    };

    uint32_t a_off[2];
#pragma unroll
    for (int mt = 0; mt < 2; mt++) {
        const int kIdx = (lane & 7) + ((lane >> 4) << 3);
        const int mOff = (lane >> 3) & 1;
        const int cm = (warp_m + mt * 16 + mOff * 8) >> 3;
        a_off[mt] = (uint32_t)kIdx * 512 + ((uint32_t)(cm ^ (lane & 7)) << 4);
    }
    uint32_t b_off[4];
#pragma unroll
    for (int p = 0; p < 4; p++) {
        const int kIdx = (lane & 7) + (((lane >> 3) & 1) << 3);
        const int nOff = lane >> 4;
        const int cn = (warp_n + p * 16 + nOff * 8) >> 3;
        b_off[p] = OFFB + (uint32_t)kIdx * 256 + ((uint32_t)(cn ^ (lane & 7)) << 4);
    }

    float acc[2][8][4];
#pragma unroll
    for (int mt = 0; mt < 2; mt++)
#pragma unroll
        for (int nt = 0; nt < 8; nt++)
#pragma unroll
            for (int r = 0; r < 4; r++) acc[mt][nt][r] = 0.f;

    load_chunk(0); load_chunk(1); load_chunk(2);

    for (int kt = 0; kt < NCHUNK; kt++) {
        mbar_wait(mb[kt & (NSTG - 1)], (kt / NSTG) & 1);
        __syncthreads();
        if (kt + 3 < NCHUNK) load_chunk(kt + 3);

        const uint32_t st = sb + (uint32_t)(kt & (NSTG - 1)) * STAGEB;
#pragma unroll
        for (int kk = 0; kk < 4; kk++) {
            uint32_t ah[2][4];
            LDSM_X4_T(ah[0], st + a_off[0] + kk * 8192);
            LDSM_X4_T(ah[1], st + a_off[1] + kk * 8192);
#pragma unroll
            for (int p = 0; p < 4; p++) {
                uint32_t bh[4];
                LDSM_X4_T(bh, st + b_off[p] + kk * 4096);
#pragma unroll
                for (int mt = 0; mt < 2; mt++) {
                    MMA_F16(acc[mt][2 * p],     ah[mt][0], ah[mt][1], ah[mt][2], ah[mt][3], bh[0], bh[1]);
                    MMA_F16(acc[mt][2 * p + 1], ah[mt][0], ah[mt][1], ah[mt][2], ah[mt][3], bh[2], bh[3]);
                }
            }
        }
    }

    // ---- epilogue ----
    const int mrow = lane >> 2;
    const int cpair = (lane & 3) * 2;
    const int which = QKV ? (n0 >> 11) : 0;
    const int nseg = QKV ? (n0 & 2047) : n0;
    const int h = nseg >> 7;
    const float* bp = QKV ? (which == 0 ? b0p : which == 1 ? b1p : b2p) : b0p;
    __half* outh = QKV ? (which == 0 ? g_Qh : which == 1 ? g_Kh : g_Vh) : nullptr;

#pragma unroll
    for (int mt = 0; mt < 2; mt++) {
#pragma unroll
        for (int rr = 0; rr < 2; rr++) {
            const int m = m0 + warp_m + mt * 16 + mrow + rr * 8;
            const int b = m >> 12;
            const int s = m & (Sc - 1);
#pragma unroll
            for (int nt = 0; nt < 8; nt++) {
                const int nl = warp_n + nt * 8 + cpair;
                float v0 = acc[mt][nt][rr * 2 + 0] + bp[nseg + nl];
                float v1 = acc[mt][nt][rr * 2 + 1] + bp[nseg + nl + 1];
                if (QKV) {
                    if (which < 2) {
                        const float cs = cosT[(size_t)s * Dc + nl];
                        const float sn = sinT[(size_t)s * Dc + nl];
                        const float e = v0 * cs - v1 * sn;
                        const float o_ = v1 * cs + v0 * sn;
                        v0 = fmaxf(e, 0.f);
                        v1 = fmaxf(o_, 0.f);
                    }
                    const size_t oi = (((size_t)b * Hc + h) * Sc + s) * Dc + nl;
                    *(uint32_t*)(outh + oi) = pack_h2(v0, v1);
                } else {
                    *(float2*)(dout + (size_t)m * Cc + nseg + nl) = make_float2(v0, v1);
                }
            }
        }
    }
}

// ======================= fp16 HMMA VK (unchanged R13) =======================
#define VROW 272
#define VK_KOFF (64 * VROW)

__global__ void __launch_bounds__(256) vk_mma()
{
    __shared__ __align__(16) char sm[2 * VK_KOFF];
    const int bh = blockIdx.x;
    const int sp = blockIdx.y;
    const int tid = threadIdx.x;
    const int lane = tid & 31;
    const int wid = tid >> 5;
    const int warp_m = (wid >> 1) * 32;
    const int warp_n = (wid & 1) * 64;
    const uint32_t sb = smem_u32(sm);

    const __half* Vg = g_Vh + (size_t)bh * Sc * Dc;
    const __half* Kg = g_Kh + (size_t)bh * Sc * Dc;

    uint32_t a_off[2];
#pragma unroll
    for (int mt = 0; mt < 2; mt++) {
        const int kIdx = (lane & 7) + ((lane >> 4) << 3);
        const int mOff = ((lane >> 3) & 1) * 8;
        a_off[mt] = (uint32_t)kIdx * VROW + (uint32_t)(warp_m + mt * 16 + mOff) * 2;
    }
    uint32_t b_off[4];
#pragma unroll
    for (int p = 0; p < 4; p++) {
        const int kIdx = (lane & 7) + (((lane >> 3) & 1) << 3);
        const int nOff = (lane >> 4) * 8;
        b_off[p] = VK_KOFF + (uint32_t)kIdx * VROW + (uint32_t)(warp_n + p * 16 + nOff) * 2;
    }

    float acc[2][8][4];
#pragma unroll
    for (int mt = 0; mt < 2; mt++)
#pragma unroll
        for (int nt = 0; nt < 8; nt++)
#pragma unroll
            for (int r = 0; r < 4; r++) acc[mt][nt][r] = 0.f;
    float csum = 0.f;

    const int sbase = sp * (Sc / NSPLIT);
    for (int ch = 0; ch < (Sc / NSPLIT) / 64; ch++) {
        const int s0 = sbase + ch * 64;
        for (int idx = tid; idx < 64 * 16; idx += 256) {
            const int r = idx >> 4, c = idx & 15;
            *(uint4*)(sm + r * VROW + c * 16) =
                *(const uint4*)(Vg + (size_t)(s0 + r) * Dc + c * 8);
            *(uint4*)(sm + VK_KOFF + r * VROW + c * 16) =
                *(const uint4*)(Kg + (size_t)(s0 + r) * Dc + c * 8);
        }
        __syncthreads();

#pragma unroll
        for (int kk = 0; kk < 4; kk++) {
            uint32_t ah[2][4];
            LDSM_X4_T(ah[0], sb + a_off[0] + kk * (16 * VROW));
            LDSM_X4_T(ah[1], sb + a_off[1] + kk * (16 * VROW));
#pragma unroll
            for (int p = 0; p < 4; p++) {
                uint32_t bh[4];
                LDSM_X4_T(bh, sb + b_off[p] + kk * (16 * VROW));
#pragma unroll
                for (int mt = 0; mt < 2; mt++) {
                    MMA_F16(acc[mt][2 * p],     ah[mt][0], ah[mt][1], ah[mt][2], ah[mt][3], bh[0], bh[1]);
                    MMA_F16(acc[mt][2 * p + 1], ah[mt][0], ah[mt][1], ah[mt][2], ah[mt][3], bh[2], bh[3]);
                }
            }
        }
        if (tid < 128) {
            const __half* kc = (const __half*)(sm + VK_KOFF) + tid;
#pragma unroll 16
            for (int r = 0; r < 64; r++)
                csum += __half2float(*(const __half*)((const char*)kc + r * VROW));
        }
        __syncthreads();
    }

    float* P = &g_VKpart[sp][(size_t)bh * 129 * Dc];
    const int mrow = lane >> 2;
    const int cpair = (lane & 3) * 2;
#pragma unroll
    for (int mt = 0; mt < 2; mt++) {
#pragma unroll
        for (int rr = 0; rr < 2; rr++) {
            const int n = warp_m + mt * 16 + mrow + rr * 8;
#pragma unroll
            for (int nt = 0; nt < 8; nt++) {
                const int d = warp_n + nt * 8 + cpair;
                *(float2*)&P[(size_t)n * Dc + d] =
                    make_float2(acc[mt][nt][rr * 2], acc[mt][nt][rr * 2 + 1]);
            }
        }
    }
    if (tid < 128) P[(size_t)128 * Dc + tid] = csum;
}

__global__ void vk_reduce()
{
    const int i = blockIdx.x * 256 + threadIdx.x;
    if (i < Bc * Hc * 129 * Dc / 2) {
        float2 s = make_float2(0.f, 0.f);
#pragma unroll
        for (int p = 0; p < NSPLIT; p++) {
            const float2 v = *(const float2*)&g_VKpart[p][(size_t)i * 2];
            s.x += v.x; s.y += v.y;
        }
        *(uint32_t*)(g_VKh + (size_t)i * 2) = pack_h2(s.x, s.y);
    }
}

// ======================= fp16 HMMA attn; writes ATT_T tiled (unchanged) ======
#define QROW 272
#define SM_VK 34816
#define SM_DEN (34816 + 35088)

__global__ void __launch_bounds__(256) attn_mma()
{
    extern __shared__ __align__(16) char sm[];
    float* den = (float*)(sm + SM_DEN);

    const int bh = blockIdx.x;
    const int b = bh >> 4, h = bh & 15;
    const int s0 = blockIdx.y * 128;
    const int tid = threadIdx.x;
    const int lane = tid & 31;
    const int wid = tid >> 5;
    const int warp_m = (wid >> 1) * 32;
    const int warp_n = (wid & 1) * 64;

    const uint32_t sb = smem_u32(sm);

    const __half* Qg = g_Qh + ((size_t)bh * Sc + s0) * Dc;
    for (int idx = tid; idx < 128 * 16; idx += 256) {
        const int r = idx >> 4, c = idx & 15;
        *(uint4*)(sm + r * QROW + c * 16) = *(const uint4*)(Qg + (size_t)r * Dc + c * 8);
    }
    const __half* VKg = g_VKh + (size_t)bh * 129 * Dc;
    for (int idx = tid; idx < 129 * 16; idx += 256) {
        const int r = idx >> 4, c = idx & 15;
        *(uint4*)(sm + SM_VK + r * QROW + c * 16) = *(const uint4*)(VKg + (size_t)r * Dc + c * 8);
    }
    __syncthreads();

    float acc[2][8][4];
#pragma unroll
    for (int mt = 0; mt < 2; mt++)
#pragma unroll
        for (int nt = 0; nt < 8; nt++)
#pragma unroll
            for (int r = 0; r < 4; r++) acc[mt][nt][r] = 0.f;

    uint32_t a_addr[2];
#pragma unroll
    for (int mt = 0; mt < 2; mt++)
        a_addr[mt] = sb + (warp_m + mt * 16 + (lane & 15)) * QROW + (lane >> 4) * 16;
    uint32_t b_addr[4];
#pragma unroll
    for (int p = 0; p < 4; p++)
        b_addr[p] = sb + SM_VK +
            (warp_n + p * 16 + ((lane >> 4) & 1) * 8 + (lane & 7)) * QROW +
            ((lane >> 3) & 1) * 16;

#pragma unroll
    for (int ks = 0; ks < 8; ks++) {
        uint32_t ah[2][4];
        LDSM_X4(ah[0], a_addr[0] + ks * 32);
        LDSM_X4(ah[1], a_addr[1] + ks * 32);
#pragma unroll
        for (int p = 0; p < 4; p++) {
            uint32_t bhreg[4];
            LDSM_X4(bhreg, b_addr[p] + ks * 32);
#pragma unroll
            for (int mt = 0; mt < 2; mt++) {
                MMA_F16(acc[mt][2 * p],     ah[mt][0], ah[mt][1], ah[mt][2], ah[mt][3], bhreg[0], bhreg[1]);
                MMA_F16(acc[mt][2 * p + 1], ah[mt][0], ah[mt][1], ah[mt][2], ah[mt][3], bhreg[2], bhreg[3]);
            }
        }
    }

    if (tid < 128) {
        const __half2* vrow = (const __half2*)(sm + SM_VK + 128 * QROW);
        const __half2* qrow = (const __half2*)(sm + tid * QROW);
        float d = 0.f;
#pragma unroll 8
        for (int i = 0; i < 64; i++) {
            const float2 v = __half22float2(vrow[i]);
            const float2 q = __half22float2(qrow[i]);
            d = fmaf(v.x, q.x, d);
            d = fmaf(v.y, q.y, d);
        }
        den[tid] = 1.0f / (d + 1e-15f);
    }
    __syncthreads();

    const int mrow = lane >> 2;
    const int cpair = (lane & 3) * 2;
#pragma unroll
    for (int mt = 0; mt < 2; mt++) {
#pragma unroll
        for (int rr = 0; rr < 2; rr++) {
            const int m = warp_m + mt * 16 + mrow + rr * 8;
            const float inv = den[m];
#pragma unroll
            for (int nt = 0; nt < 8; nt++) {
                const int n = warp_n + nt * 8 + cpair;
                *(uint32_t*)(sm + m * QROW + n * 2) =
                    pack_h2(acc[mt][nt][rr * 2] * inv, acc[mt][nt][rr * 2 + 1] * inv);
            }
        }
    }
    __syncthreads();

    const int mbase = b * Sc + s0;
    const int mblk = mbase >> 8;
    const int cb = (mbase & 255) >> 3;
    for (int ci = tid; ci < 128 * 16; ci += 256) {
        const int c_loc = ci >> 4, p = ci & 15;
        const int c = h * 128 + c_loc;
        const int cl = p ^ (c & 7);
        __half v[8];
#pragma unroll
        for (int j = 0; j < 8; j++)
            v[j] = *(__half*)(sm + (cl * 8 + j) * QROW + c_loc * 2);
        __half* o = g_ATT_T + (size_t)mblk * 524288 + (size_t)c * 256 + (cb + p) * 8;
        *(uint4*)o = *(uint4*)v;
    }
}

// ======================= launch =======================
extern "C" void kernel_launch(void* const* d_in, const int* in_sizes, int n_in,
                              void* d_out, int out_size)
{
    (void)in_sizes; (void)n_in; (void)out_size;
    const float* x    = (const float*)d_in[0];
    const float* cosT = (const float*)d_in[1];
    const float* sinT = (const float*)d_in[2];
    const float* Wq   = (const float*)d_in[3];
    const float* bq   = (const float*)d_in[4];
    const float* Wk   = (const float*)d_in[5];
    const float* bk   = (const float*)d_in[6];
    const float* Wv   = (const float*)d_in[7];
    const float* bv   = (const float*)d_in[8];
    const float* Wo   = (const float*)d_in[9];
    const float* bo   = (const float*)d_in[10];
    float* out = (float*)d_out;

    __half *xT, *wT, *attT;
    cudaGetSymbolAddress((void**)&xT, g_XT);
    cudaGetSymbolAddress((void**)&wT, g_WT);
    cudaGetSymbolAddress((void**)&attT, g_ATT_T);

    const size_t WTM = (size_t)16 * 262144;
    convert_x<<<dim3(32, 128), 256>>>(x, xT);
    convert_w<<<dim3(32, 32, 4), 256>>>(Wq, Wk, Wv, Wo, wT);

    const int gsm = NSTG * STAGEB;   // 196608
    cudaFuncSetAttribute(mma_gemm<0>, cudaFuncAttributeMaxDynamicSharedMemorySize, gsm);
    cudaFuncSetAttribute(mma_gemm<1>, cudaFuncAttributeMaxDynamicSharedMemorySize, gsm);

    // merged QKV: N = 6144, grid (48, 32)
    mma_gemm<1><<<dim3(48, 32), NT, gsm>>>(xT, wT, bq, bk, bv, cosT, sinT, nullptr);

    vk_mma<<<dim3(Bc * Hc, NSPLIT), 256>>>();
    vk_reduce<<<(Bc * Hc * 129 * Dc / 2 + 255) / 256, 256>>>();

    const int asm_ = SM_DEN + 128 * sizeof(float) + 16;   // ~70.4KB
    cudaFuncSetAttribute(attn_mma, cudaFuncAttributeMaxDynamicSharedMemorySize, asm_);
    attn_mma<<<dim3(Bc * Hc, Sc / 128), 256, asm_>>>();

    // O projection
    mma_gemm<0><<<dim3(16, 32), NT, gsm>>>(attT, wT + 3 * WTM, bo, bo, bo,
                                           nullptr, nullptr, out);
}

// round 15
// speedup vs baseline: 1.0953x; 1.0953x over previous
#include <cuda_runtime.h>
#include <cuda_fp16.h>
#include <cstdint>
#include <cstddef>

#define Bc 2
#define Sc 4096
#define Cc 2048
#define Hc 16
#define Dc 128
#define NSPLIT 16

// ---------------- scratch (device globals; no allocation) ----------------
__device__ float g_VKpart[NSPLIT][(size_t)Bc * Hc * 129 * Dc];
__device__ __half g_Qh[(size_t)Bc * Hc * Sc * Dc];   // fp16 (b,h,s,d)
__device__ __half g_Kh[(size_t)Bc * Hc * Sc * Dc];
__device__ __half g_Vh[(size_t)Bc * Hc * Sc * Dc];
__device__ __half g_VKh[(size_t)Bc * Hc * 129 * Dc]; // fp16
// K-major tiled+swizzled operands
__device__ __half g_XT[(size_t)32 * 2048 * 256];     // x^T  [mblk][k][mi]
__device__ __half g_WT[(size_t)64 * 2048 * 128];     // qkv|o [nblk][k][ni]
__device__ __half g_ATT_T[(size_t)32 * 2048 * 256];  // attn out, same as XT

// ======================= helpers =======================
__device__ __forceinline__ uint32_t smem_u32(const void* p) {
    return (uint32_t)__cvta_generic_to_shared(p);
}
__device__ __forceinline__ uint32_t pack_h2(float x, float y) {
    __half2 h = __floats2half2_rn(x, y);
    return *reinterpret_cast<uint32_t*>(&h);
}
__device__ __forceinline__ void mbar_init(uint32_t a, uint32_t cnt) {
    asm volatile("mbarrier.init.shared.b64 [%0], %1;" :: "r"(a), "r"(cnt) : "memory");
}
__device__ __forceinline__ void mbar_expect_tx(uint32_t a, uint32_t bytes) {
    asm volatile("mbarrier.arrive.expect_tx.shared.b64 _, [%0], %1;"
                 :: "r"(a), "r"(bytes) : "memory");
}
__device__ __forceinline__ void mbar_wait(uint32_t a, uint32_t parity) {
    uint32_t done = 0;
    while (!done) {
        asm volatile(
            "{\n\t.reg .pred p;\n\t"
            "mbarrier.try_wait.parity.acquire.cta.shared::cta.b64 p, [%1], %2, 0x989680;\n\t"
            "selp.b32 %0, 1, 0, p;\n\t}"
            : "=r"(done) : "r"(a), "r"(parity) : "memory");
    }
}
__device__ __forceinline__ void bulk_g2s(uint32_t dst, const void* src,
                                         uint32_t bytes, uint32_t mbar) {
    asm volatile(
        "cp.async.bulk.shared::cluster.global.mbarrier::complete_tx::bytes "
        "[%0], [%1], %2, [%3];"
        :: "r"(dst), "l"(__cvta_generic_to_global(src)), "r"(bytes), "r"(mbar)
        : "memory");
}

#define LDSM_X4(r, addr) \
    asm volatile("ldmatrix.sync.aligned.m8n8.x4.shared.b16 {%0,%1,%2,%3}, [%4];" \
        : "=r"((r)[0]), "=r"((r)[1]), "=r"((r)[2]), "=r"((r)[3]) : "r"(addr))
#define LDSM_X4_T(r, addr) \
    asm volatile("ldmatrix.sync.aligned.m8n8.x4.trans.shared.b16 {%0,%1,%2,%3}, [%4];" \
        : "=r"((r)[0]), "=r"((r)[1]), "=r"((r)[2]), "=r"((r)[3]) : "r"(addr))
#define MMA_F16(d, a0, a1, a2, a3, b0, b1) \
    asm volatile("mma.sync.aligned.m16n8k16.row.col.f32.f16.f16.f32 " \
        "{%0,%1,%2,%3}, {%4,%5,%6,%7}, {%8,%9}, {%0,%1,%2,%3};" \
        : "+f"((d)[0]), "+f"((d)[1]), "+f"((d)[2]), "+f"((d)[3]) \
        : "r"(a0), "r"(a1), "r"(a2), "r"(a3), "r"(b0), "r"(b1))

// ======================= fp32 -> fp16 K-major tiled+swizzled transpose ======
// float4 loads (16B) -> half the LDG issue count of the float2 version.
__device__ __forceinline__ void convert_tile(const float* __restrict__ src,
                                             __half* __restrict__ dst,
                                             int k0, int m0, int blkShift, int tid)
{
    __shared__ __half ts[64][72];

    for (int idx = tid; idx < 64 * 16; idx += 256) {
        const int ml = idx >> 4, kq = idx & 15;
        const float4 f = *(const float4*)(src + (size_t)(m0 + ml) * 2048 + k0 + kq * 4);
        *(uint32_t*)&ts[ml][kq * 4]     = pack_h2(f.x, f.y);
        *(uint32_t*)&ts[ml][kq * 4 + 2] = pack_h2(f.z, f.w);
    }
    __syncthreads();

    const int blkM = 1 << blkShift;
    const int mblk = m0 >> blkShift;
    const int b0 = (m0 & (blkM - 1)) >> 3;
    const size_t blkElems = (size_t)2048 << blkShift;

    for (int ci = tid; ci < 512; ci += 256) {
        const int kl = ci >> 3, p = ci & 7;
        const int k = k0 + kl;
        const int cl = p ^ (k & 7);
        __half v[8];
#pragma unroll
        for (int j = 0; j < 8; j++) v[j] = ts[cl * 8 + j][kl];
        __half* o = dst + (size_t)mblk * blkElems + (size_t)k * blkM + (b0 + p) * 8;
        *(uint4*)o = *(uint4*)v;
    }
}

__global__ void convert_x(const float* __restrict__ src, __half* __restrict__ dst)
{
    convert_tile(src, dst, blockIdx.x * 64, blockIdx.y * 64, 8, threadIdx.x);
}
__global__ void convert_w(const float* __restrict__ w0, const float* __restrict__ w1,
                          const float* __restrict__ w2, const float* __restrict__ w3,
                          __half* __restrict__ dst)
{
    const float* w = (blockIdx.z == 0) ? w0 : (blockIdx.z == 1) ? w1
                   : (blockIdx.z == 2) ? w2 : w3;
    convert_tile(w, dst + (size_t)blockIdx.z * (16 * 262144),
                 blockIdx.x * 64, blockIdx.y * 64, 7, threadIdx.x);
}

// ======================= fp16 HMMA GEMM (R13 proven: 2-stage, KCH 128) ======
#define KCH 128
#define NCHUNK (Cc / KCH)          // 16
#define OFFB 65536
#define STAGEB 98304
#define TXBYTES 98304
#define NT 512

template <int QKV>
__global__ void __launch_bounds__(NT, 1) mma_gemm(
    const __half* __restrict__ Ah, const __half* __restrict__ Bh,
    const float* __restrict__ b0p, const float* __restrict__ b1p,
    const float* __restrict__ b2p,
    const float* __restrict__ cosT, const float* __restrict__ sinT,
    float* __restrict__ dout)
{
    extern __shared__ __align__(16) char dyn[];
    __shared__ __align__(8) uint64_t mbar_store[2];

    const int tid = threadIdx.x;
    const int lane = tid & 31;
    const int wid = tid >> 5;
    const int m0 = blockIdx.y * 256;
    const int n0 = blockIdx.x * 128;
    const int warp_m = (wid >> 1) * 32;
    const int warp_n = (wid & 1) * 64;

    const uint32_t sb = smem_u32(dyn);
    const uint32_t mb0 = smem_u32(&mbar_store[0]);
    const uint32_t mb1 = smem_u32(&mbar_store[1]);

    if (tid == 0) { mbar_init(mb0, 1); mbar_init(mb1, 1); }
    __syncthreads();

    const __half* aBase = Ah + (size_t)blockIdx.y * (2048 * 256);
    const __half* bBase = Bh + (size_t)blockIdx.x * (2048 * 128);

    auto load_chunk = [&](int kt) {
        if (tid == 0) {
            const uint32_t st = sb + (uint32_t)(kt & 1) * STAGEB;
            const uint32_t bar = (kt & 1) ? mb1 : mb0;
            mbar_expect_tx(bar, TXBYTES);
            bulk_g2s(st, aBase + (size_t)kt * (KCH * 256), 65536, bar);
            bulk_g2s(st + OFFB, bBase + (size_t)kt * (KCH * 128), 32768, bar);
        }
    };

    uint32_t a_off[2];
#pragma unroll
    for (int mt = 0; mt < 2; mt++) {
        const int kIdx = (lane & 7) + ((lane >> 4) << 3);
        const int mOff = (lane >> 3) & 1;
        const int cm = (warp_m + mt * 16 + mOff * 8) >> 3;
        a_off[mt] = (uint32_t)kIdx * 512 + ((uint32_t)(cm ^ (lane & 7)) << 4);
    }
    uint32_t b_off[4];
#pragma unroll
    for (int p = 0; p < 4; p++) {
        const int kIdx = (lane & 7) + (((lane >> 3) & 1) << 3);
        const int nOff = lane >> 4;
        const int cn = (warp_n + p * 16 + nOff * 8) >> 3;
        b_off[p] = OFFB + (uint32_t)kIdx * 256 + ((uint32_t)(cn ^ (lane & 7)) << 4);
    }

    float acc[2][8][4];
#pragma unroll
    for (int mt = 0; mt < 2; mt++)
#pragma unroll
        for (int nt = 0; nt < 8; nt++)
#pragma unroll
            for (int r = 0; r < 4; r++) acc[mt][nt][r] = 0.f;

    load_chunk(0);

    for (int kt = 0; kt < NCHUNK; kt++) {
        mbar_wait((kt & 1) ? mb1 : mb0, (kt >> 1) & 1);
        __syncthreads();
        if (kt + 1 < NCHUNK) load_chunk(kt + 1);

        const uint32_t st = sb + (uint32_t)(kt & 1) * STAGEB;
#pragma unroll
        for (int kk = 0; kk < 8; kk++) {
            uint32_t ah[2][4];
            LDSM_X4_T(ah[0], st + a_off[0] + kk * 8192);
            LDSM_X4_T(ah[1], st + a_off[1] + kk * 8192);
#pragma unroll
            for (int p = 0; p < 4; p++) {
                uint32_t bh[4];
                LDSM_X4_T(bh, st + b_off[p] + kk * 4096);
#pragma unroll
                for (int mt = 0; mt < 2; mt++) {
                    MMA_F16(acc[mt][2 * p],     ah[mt][0], ah[mt][1], ah[mt][2], ah[mt][3], bh[0], bh[1]);
                    MMA_F16(acc[mt][2 * p + 1], ah[mt][0], ah[mt][1], ah[mt][2], ah[mt][3], bh[2], bh[3]);
                }
            }
        }
    }

    // ---- epilogue ----
    const int mrow = lane >> 2;
    const int cpair = (lane & 3) * 2;
    const int which = QKV ? (n0 >> 11) : 0;
    const int nseg = QKV ? (n0 & 2047) : n0;
    const int h = nseg >> 7;
    const float* bp = QKV ? (which == 0 ? b0p : which == 1 ? b1p : b2p) : b0p;
    __half* outh = QKV ? (which == 0 ? g_Qh : which == 1 ? g_Kh : g_Vh) : nullptr;

#pragma unroll
    for (int mt = 0; mt < 2; mt++) {
#pragma unroll
        for (int rr = 0; rr < 2; rr++) {
            const int m = m0 + warp_m + mt * 16 + mrow + rr * 8;
            const int b = m >> 12;
            const int s = m & (Sc - 1);
#pragma unroll
            for (int nt = 0; nt < 8; nt++) {
                const int nl = warp_n + nt * 8 + cpair;
                float v0 = acc[mt][nt][rr * 2 + 0] + bp[nseg + nl];
                float v1 = acc[mt][nt][rr * 2 + 1] + bp[nseg + nl + 1];
                if (QKV) {
                    if (which < 2) {
                        const float cs = cosT[(size_t)s * Dc + nl];
                        const float sn = sinT[(size_t)s * Dc + nl];
                        const float e = v0 * cs - v1 * sn;
                        const float o_ = v1 * cs + v0 * sn;
                        v0 = fmaxf(e, 0.f);
                        v1 = fmaxf(o_, 0.f);
                    }
                    const size_t oi = (((size_t)b * Hc + h) * Sc + s) * Dc + nl;
                    *(uint32_t*)(outh + oi) = pack_h2(v0, v1);
                } else {
                    *(float2*)(dout + (size_t)m * Cc + nseg + nl) = make_float2(v0, v1);
                }
            }
        }
    }
}

// ======================= fp16 HMMA VK (NSPLIT=16 for occupancy) =============
#define VROW 272
#define VK_KOFF (64 * VROW)

__global__ void __launch_bounds__(256) vk_mma()
{
    __shared__ __align__(16) char sm[2 * VK_KOFF];
    const int bh = blockIdx.x;
    const int sp = blockIdx.y;
    const int tid = threadIdx.x;
    const int lane = tid & 31;
    const int wid = tid >> 5;
    const int warp_m = (wid >> 1) * 32;
    const int warp_n = (wid & 1) * 64;
    const uint32_t sb = smem_u32(sm);

    const __half* Vg = g_Vh + (size_t)bh * Sc * Dc;
    const __half* Kg = g_Kh + (size_t)bh * Sc * Dc;

    uint32_t a_off[2];
#pragma unroll
    for (int mt = 0; mt < 2; mt++) {
        const int kIdx = (lane & 7) + ((lane >> 4) << 3);
        const int mOff = ((lane >> 3) & 1) * 8;
        a_off[mt] = (uint32_t)kIdx * VROW + (uint32_t)(warp_m + mt * 16 + mOff) * 2;
    }
    uint32_t b_off[4];
#pragma unroll
    for (int p = 0; p < 4; p++) {
        const int kIdx = (lane & 7) + (((lane >> 3) & 1) << 3);
        const int nOff = (lane >> 4) * 8;
        b_off[p] = VK_KOFF + (uint32_t)kIdx * VROW + (uint32_t)(warp_n + p * 16 + nOff) * 2;
    }

    float acc[2][8][4];
#pragma unroll
    for (int mt = 0; mt < 2; mt++)
#pragma unroll
        for (int nt = 0; nt < 8; nt++)
#pragma unroll
            for (int r = 0; r < 4; r++) acc[mt][nt][r] = 0.f;
    float csum = 0.f;

    const int sbase = sp * (Sc / NSPLIT);
    for (int ch = 0; ch < (Sc / NSPLIT) / 64; ch++) {
        const int s0 = sbase + ch * 64;
        for (int idx = tid; idx < 64 * 16; idx += 256) {
            const int r = idx >> 4, c = idx & 15;
            *(uint4*)(sm + r * VROW + c * 16) =
                *(const uint4*)(Vg + (size_t)(s0 + r) * Dc + c * 8);
            *(uint4*)(sm + VK_KOFF + r * VROW + c * 16) =
                *(const uint4*)(Kg + (size_t)(s0 + r) * Dc + c * 8);
        }
        __syncthreads();

#pragma unroll
        for (int kk = 0; kk < 4; kk++) {
            uint32_t ah[2][4];
            LDSM_X4_T(ah[0], sb + a_off[0] + kk * (16 * VROW));
            LDSM_X4_T(ah[1], sb + a_off[1] + kk * (16 * VROW));
#pragma unroll
            for (int p = 0; p < 4; p++) {
                uint32_t bh[4];
                LDSM_X4_T(bh, sb + b_off[p] + kk * (16 * VROW));
#pragma unroll
                for (int mt = 0; mt < 2; mt++) {
                    MMA_F16(acc[mt][2 * p],     ah[mt][0], ah[mt][1], ah[mt][2], ah[mt][3], bh[0], bh[1]);
                    MMA_F16(acc[mt][2 * p + 1], ah[mt][0], ah[mt][1], ah[mt][2], ah[mt][3], bh[2], bh[3]);
                }
            }
        }
        if (tid < 128) {
            const __half* kc = (const __half*)(sm + VK_KOFF) + tid;
#pragma unroll 16
            for (int r = 0; r < 64; r++)
                csum += __half2float(*(const __half*)((const char*)kc + r * VROW));
        }
        __syncthreads();
    }

    float* P = &g_VKpart[sp][(size_t)bh * 129 * Dc];
    const int mrow = lane >> 2;
    const int cpair = (lane & 3) * 2;
#pragma unroll
    for (int mt = 0; mt < 2; mt++) {
#pragma unroll
        for (int rr = 0; rr < 2; rr++) {
            const int n = warp_m + mt * 16 + mrow + rr * 8;
#pragma unroll
            for (int nt = 0; nt < 8; nt++) {
                const int d = warp_n + nt * 8 + cpair;
                *(float2*)&P[(size_t)n * Dc + d] =
                    make_float2(acc[mt][nt][rr * 2], acc[mt][nt][rr * 2 + 1]);
            }
        }
    }
    if (tid < 128) P[(size_t)128 * Dc + tid] = csum;
}

__global__ void vk_reduce()
{
    const int i = blockIdx.x * 256 + threadIdx.x;
    if (i < Bc * Hc * 129 * Dc / 2) {
        float2 s = make_float2(0.f, 0.f);
#pragma unroll
        for (int p = 0; p < NSPLIT; p++) {
            const float2 v = *(const float2*)&g_VKpart[p][(size_t)i * 2];
            s.x += v.x; s.y += v.y;
        }
        *(uint32_t*)(g_VKh + (size_t)i * 2) = pack_h2(s.x, s.y);
    }
}

// ======================= fp16 HMMA attn; writes ATT_T tiled (unchanged) ======
#define QROW 272
#define SM_VK 34816
#define SM_DEN (34816 + 35088)

__global__ void __launch_bounds__(256) attn_mma()
{
    extern __shared__ __align__(16) char sm[];
    float* den = (float*)(sm + SM_DEN);

    const int bh = blockIdx.x;
    const int b = bh >> 4, h = bh & 15;
    const int s0 = blockIdx.y * 128;
    const int tid = threadIdx.x;
    const int lane = tid & 31;
    const int wid = tid >> 5;
    const int warp_m = (wid >> 1) * 32;
    const int warp_n = (wid & 1) * 64;

    const uint32_t sb = smem_u32(sm);

    const __half* Qg = g_Qh + ((size_t)bh * Sc + s0) * Dc;
    for (int idx = tid; idx < 128 * 16; idx += 256) {
        const int r = idx >> 4, c = idx & 15;
        *(uint4*)(sm + r * QROW + c * 16) = *(const uint4*)(Qg + (size_t)r * Dc + c * 8);
    }
    const __half* VKg = g_VKh + (size_t)bh * 129 * Dc;
    for (int idx = tid; idx < 129 * 16; idx += 256) {
        const int r = idx >> 4, c = idx & 15;
        *(uint4*)(sm + SM_VK + r * QROW + c * 16) = *(const uint4*)(VKg + (size_t)r * Dc + c * 8);
    }
    __syncthreads();

    float acc[2][8][4];
#pragma unroll
    for (int mt = 0; mt < 2; mt++)
#pragma unroll
        for (int nt = 0; nt < 8; nt++)
#pragma unroll
            for (int r = 0; r < 4; r++) acc[mt][nt][r] = 0.f;

    uint32_t a_addr[2];
#pragma unroll
    for (int mt = 0; mt < 2; mt++)
        a_addr[mt] = sb + (warp_m + mt * 16 + (lane & 15)) * QROW + (lane >> 4) * 16;
    uint32_t b_addr[4];
#pragma unroll
    for (int p = 0; p < 4; p++)
        b_addr[p] = sb + SM_VK +
            (warp_n + p * 16 + ((lane >> 4) & 1) * 8 + (lane & 7)) * QROW +
            ((lane >> 3) & 1) * 16;

#pragma unroll
    for (int ks = 0; ks < 8; ks++) {
        uint32_t ah[2][4];
        LDSM_X4(ah[0], a_addr[0] + ks * 32);
        LDSM_X4(ah[1], a_addr[1] + ks * 32);
#pragma unroll
        for (int p = 0; p < 4; p++) {
            uint32_t bhreg[4];
            LDSM_X4(bhreg, b_addr[p] + ks * 32);
#pragma unroll
            for (int mt = 0; mt < 2; mt++) {
                MMA_F16(acc[mt][2 * p],     ah[mt][0], ah[mt][1], ah[mt][2], ah[mt][3], bhreg[0], bhreg[1]);
                MMA_F16(acc[mt][2 * p + 1], ah[mt][0], ah[mt][1], ah[mt][2], ah[mt][3], bhreg[2], bhreg[3]);
            }
        }
    }

    if (tid < 128) {
        const __half2* vrow = (const __half2*)(sm + SM_VK + 128 * QROW);
        const __half2* qrow = (const __half2*)(sm + tid * QROW);
        float d = 0.f;
#pragma unroll 8
        for (int i = 0; i < 64; i++) {
            const float2 v = __half22float2(vrow[i]);
            const float2 q = __half22float2(qrow[i]);
            d = fmaf(v.x, q.x, d);
            d = fmaf(v.y, q.y, d);
        }
        den[tid] = 1.0f / (d + 1e-15f);
    }
    __syncthreads();

    const int mrow = lane >> 2;
    const int cpair = (lane & 3) * 2;
#pragma unroll
    for (int mt = 0; mt < 2; mt++) {
#pragma unroll
        for (int rr = 0; rr < 2; rr++) {
            const int m = warp_m + mt * 16 + mrow + rr * 8;
            const float inv = den[m];
#pragma unroll
            for (int nt = 0; nt < 8; nt++) {
                const int n = warp_n + nt * 8 + cpair;
                *(uint32_t*)(sm + m * QROW + n * 2) =
                    pack_h2(acc[mt][nt][rr * 2] * inv, acc[mt][nt][rr * 2 + 1] * inv);
            }
        }
    }
    __syncthreads();

    const int mbase = b * Sc + s0;
    const int mblk = mbase >> 8;
    const int cb = (mbase & 255) >> 3;
    for (int ci = tid; ci < 128 * 16; ci += 256) {
        const int c_loc = ci >> 4, p = ci & 15;
        const int c = h * 128 + c_loc;
        const int cl = p ^ (c & 7);
        __half v[8];
#pragma unroll
        for (int j = 0; j < 8; j++)
            v[j] = *(__half*)(sm + (cl * 8 + j) * QROW + c_loc * 2);
        __half* o = g_ATT_T + (size_t)mblk * 524288 + (size_t)c * 256 + (cb + p) * 8;
        *(uint4*)o = *(uint4*)v;
    }
}

// ======================= launch =======================
extern "C" void kernel_launch(void* const* d_in, const int* in_sizes, int n_in,
                              void* d_out, int out_size)
{
    (void)in_sizes; (void)n_in; (void)out_size;
    const float* x    = (const float*)d_in[0];
    const float* cosT = (const float*)d_in[1];
    const float* sinT = (const float*)d_in[2];
    const float* Wq   = (const float*)d_in[3];
    const float* bq   = (const float*)d_in[4];
    const float* Wk   = (const float*)d_in[5];
    const float* bk   = (const float*)d_in[6];
    const float* Wv   = (const float*)d_in[7];
    const float* bv   = (const float*)d_in[8];
    const float* Wo   = (const float*)d_in[9];
    const float* bo   = (const float*)d_in[10];
    float* out = (float*)d_out;

    __half *xT, *wT, *attT;
    cudaGetSymbolAddress((void**)&xT, g_XT);
    cudaGetSymbolAddress((void**)&wT, g_WT);
    cudaGetSymbolAddress((void**)&attT, g_ATT_T);

    const size_t WTM = (size_t)16 * 262144;
    convert_x<<<dim3(32, 128), 256>>>(x, xT);
    convert_w<<<dim3(32, 32, 4), 256>>>(Wq, Wk, Wv, Wo, wT);

    const int gsm = 2 * STAGEB;   // 196608
    cudaFuncSetAttribute(mma_gemm<0>, cudaFuncAttributeMaxDynamicSharedMemorySize, gsm);
    cudaFuncSetAttribute(mma_gemm<1>, cudaFuncAttributeMaxDynamicSharedMemorySize, gsm);

    // merged QKV: N = 6144, grid (48, 32)
    mma_gemm<1><<<dim3(48, 32), NT, gsm>>>(xT, wT, bq, bk, bv, cosT, sinT, nullptr);

    vk_mma<<<dim3(Bc * Hc, NSPLIT), 256>>>();
    vk_reduce<<<(Bc * Hc * 129 * Dc / 2 + 255) / 256, 256>>>();

    const int asm_ = SM_DEN + 128 * sizeof(float) + 16;   // ~70.4KB
    cudaFuncSetAttribute(attn_mma, cudaFuncAttributeMaxDynamicSharedMemorySize, asm_);
    attn_mma<<<dim3(Bc * Hc, Sc / 128), 256, asm_>>>();

    // O projection
    mma_gemm<0><<<dim3(16, 32), NT, gsm>>>(attT, wT + 3 * WTM, bo, bo, bo,
                                           nullptr, nullptr, out);
}

// round 16
// speedup vs baseline: 1.1062x; 1.0100x over previous
#include <cuda_runtime.h>
#include <cuda_fp16.h>
#include <cstdint>
#include <cstddef>

#define Bc 2
#define Sc 4096
#define Cc 2048
#define Hc 16
#define Dc 128
#define NSPLIT 8

// ---------------- scratch (device globals; no allocation) ----------------
__device__ float g_VKpart[NSPLIT][(size_t)Bc * Hc * 129 * Dc];
__device__ __half g_Qh[(size_t)Bc * Hc * Sc * Dc];   // fp16 (b,h,s,d)
__device__ __half g_Kh[(size_t)Bc * Hc * Sc * Dc];
__device__ __half g_Vh[(size_t)Bc * Hc * Sc * Dc];
__device__ __half g_VKh[(size_t)Bc * Hc * 129 * Dc]; // fp16
// K-major tiled+swizzled operands
__device__ __half g_XT[(size_t)32 * 2048 * 256];     // x^T  [mblk][k][mi]
__device__ __half g_WT[(size_t)64 * 2048 * 128];     // qkv|o [nblk][k][ni]
__device__ __half g_ATT_T[(size_t)32 * 2048 * 256];  // attn out, same as XT

// ======================= helpers =======================
__device__ __forceinline__ uint32_t smem_u32(const void* p) {
    return (uint32_t)__cvta_generic_to_shared(p);
}
__device__ __forceinline__ uint32_t pack_h2(float x, float y) {
    __half2 h = __floats2half2_rn(x, y);
    return *reinterpret_cast<uint32_t*>(&h);
}
__device__ __forceinline__ void mbar_init(uint32_t a, uint32_t cnt) {
    asm volatile("mbarrier.init.shared.b64 [%0], %1;" :: "r"(a), "r"(cnt) : "memory");
}
__device__ __forceinline__ void mbar_expect_tx(uint32_t a, uint32_t bytes) {
    asm volatile("mbarrier.arrive.expect_tx.shared.b64 _, [%0], %1;"
                 :: "r"(a), "r"(bytes) : "memory");
}
__device__ __forceinline__ void mbar_wait(uint32_t a, uint32_t parity) {
    uint32_t done = 0;
    while (!done) {
        asm volatile(
            "{\n\t.reg .pred p;\n\t"
            "mbarrier.try_wait.parity.acquire.cta.shared::cta.b64 p, [%1], %2, 0x989680;\n\t"
            "selp.b32 %0, 1, 0, p;\n\t}"
            : "=r"(done) : "r"(a), "r"(parity) : "memory");
    }
}
__device__ __forceinline__ void bulk_g2s(uint32_t dst, const void* src,
                                         uint32_t bytes, uint32_t mbar) {
    asm volatile(
        "cp.async.bulk.shared::cluster.global.mbarrier::complete_tx::bytes "
        "[%0], [%1], %2, [%3];"
        :: "r"(dst), "l"(__cvta_generic_to_global(src)), "r"(bytes), "r"(mbar)
        : "memory");
}

#define LDSM_X4(r, addr) \
    asm volatile("ldmatrix.sync.aligned.m8n8.x4.shared.b16 {%0,%1,%2,%3}, [%4];" \
        : "=r"((r)[0]), "=r"((r)[1]), "=r"((r)[2]), "=r"((r)[3]) : "r"(addr))
#define LDSM_X4_T(r, addr) \
    asm volatile("ldmatrix.sync.aligned.m8n8.x4.trans.shared.b16 {%0,%1,%2,%3}, [%4];" \
        : "=r"((r)[0]), "=r"((r)[1]), "=r"((r)[2]), "=r"((r)[3]) : "r"(addr))
#define MMA_F16(d, a0, a1, a2, a3, b0, b1) \
    asm volatile("mma.sync.aligned.m16n8k16.row.col.f32.f16.f16.f32 " \
        "{%0,%1,%2,%3}, {%4,%5,%6,%7}, {%8,%9}, {%0,%1,%2,%3};" \
        : "+f"((d)[0]), "+f"((d)[1]), "+f"((d)[2]), "+f"((d)[3]) \
        : "r"(a0), "r"(a1), "r"(a2), "r"(a3), "r"(b0), "r"(b1))

// ======================= fp32 -> fp16 K-major tiled+swizzled transpose ======
__device__ __forceinline__ void convert_tile(const float* __restrict__ src,
                                             __half* __restrict__ dst,
                                             int k0, int m0, int blkShift, int tid)
{
    __shared__ __half ts[64][72];

    for (int idx = tid; idx < 64 * 16; idx += 256) {
        const int ml = idx >> 4, kq = idx & 15;
        const float4 f = *(const float4*)(src + (size_t)(m0 + ml) * 2048 + k0 + kq * 4);
        *(uint32_t*)&ts[ml][kq * 4]     = pack_h2(f.x, f.y);
        *(uint32_t*)&ts[ml][kq * 4 + 2] = pack_h2(f.z, f.w);
    }
    __syncthreads();

    const int blkM = 1 << blkShift;
    const int mblk = m0 >> blkShift;
    const int b0 = (m0 & (blkM - 1)) >> 3;
    const size_t blkElems = (size_t)2048 << blkShift;

    for (int ci = tid; ci < 512; ci += 256) {
        const int kl = ci >> 3, p = ci & 7;
        const int k = k0 + kl;
        const int cl = p ^ (k & 7);
        __half v[8];
#pragma unroll
        for (int j = 0; j < 8; j++) v[j] = ts[cl * 8 + j][kl];
        __half* o = dst + (size_t)mblk * blkElems + (size_t)k * blkM + (b0 + p) * 8;
        *(uint4*)o = *(uint4*)v;
    }
}

// one launch: y<128 -> x (blkShift 8); y>=128 -> weight (y-128)>>5 (blkShift 7)
__global__ void convert_all(const float* __restrict__ x,
                            const float* __restrict__ w0, const float* __restrict__ w1,
                            const float* __restrict__ w2, const float* __restrict__ w3,
                            __half* __restrict__ xT, __half* __restrict__ wT)
{
    const int y = blockIdx.y;
    if (y < 128) {
        convert_tile(x, xT, blockIdx.x * 64, y * 64, 8, threadIdx.x);
    } else {
        const int wsel = (y - 128) >> 5;
        const int m0 = ((y - 128) & 31) * 64;
        const float* w = (wsel == 0) ? w0 : (wsel == 1) ? w1 : (wsel == 2) ? w2 : w3;
        convert_tile(w, wT + (size_t)wsel * (16 * 262144),
                     blockIdx.x * 64, m0, 7, threadIdx.x);
    }
}

// ======================= fp16 HMMA GEMM (R13 proven: 2-stage, KCH 128) ======
#define KCH 128
#define NCHUNK (Cc / KCH)          // 16
#define OFFB 65536
#define STAGEB 98304
#define TXBYTES 98304
#define NT 512

template <int QKV>
__global__ void __launch_bounds__(NT, 1) mma_gemm(
    const __half* __restrict__ Ah, const __half* __restrict__ Bh,
    const float* __restrict__ b0p, const float* __restrict__ b1p,
    const float* __restrict__ b2p,
    const float* __restrict__ cosT, const float* __restrict__ sinT,
    float* __restrict__ dout)
{
    extern __shared__ __align__(16) char dyn[];
    __shared__ __align__(8) uint64_t mbar_store[2];

    const int tid = threadIdx.x;
    const int lane = tid & 31;
    const int wid = tid >> 5;
    const int m0 = blockIdx.y * 256;
    const int n0 = blockIdx.x * 128;
    const int warp_m = (wid >> 1) * 32;
    const int warp_n = (wid & 1) * 64;

    const uint32_t sb = smem_u32(dyn);
    const uint32_t mb0 = smem_u32(&mbar_store[0]);
    const uint32_t mb1 = smem_u32(&mbar_store[1]);

    if (tid == 0) { mbar_init(mb0, 1); mbar_init(mb1, 1); }
    __syncthreads();

    const __half* aBase = Ah + (size_t)blockIdx.y * (2048 * 256);
    const __half* bBase = Bh + (size_t)blockIdx.x * (2048 * 128);

    auto load_chunk = [&](int kt) {
        if (tid == 0) {
            const uint32_t st = sb + (uint32_t)(kt & 1) * STAGEB;
            const uint32_t bar = (kt & 1) ? mb1 : mb0;
            mbar_expect_tx(bar, TXBYTES);
            bulk_g2s(st, aBase + (size_t)kt * (KCH * 256), 65536, bar);
            bulk_g2s(st + OFFB, bBase + (size_t)kt * (KCH * 128), 32768, bar);
        }
    };

    uint32_t a_off[2];
#pragma unroll
    for (int mt = 0; mt < 2; mt++) {
        const int kIdx = (lane & 7) + ((lane >> 4) << 3);
        const int mOff = (lane >> 3) & 1;
        const int cm = (warp_m + mt * 16 + mOff * 8) >> 3;
        a_off[mt] = (uint32_t)kIdx * 512 + ((uint32_t)(cm ^ (lane & 7)) << 4);
    }
    uint32_t b_off[4];
#pragma unroll
    for (int p = 0; p < 4; p++) {
        const int kIdx = (lane & 7) + (((lane >> 3) & 1) << 3);
        const int nOff = lane >> 4;
        const int cn = (warp_n + p * 16 + nOff * 8) >> 3;
        b_off[p] = OFFB + (uint32_t)kIdx * 256 + ((uint32_t)(cn ^ (lane & 7)) << 4);
    }

    float acc[2][8][4];
#pragma unroll
    for (int mt = 0; mt < 2; mt++)
#pragma unroll
        for (int nt = 0; nt < 8; nt++)
#pragma unroll
            for (int r = 0; r < 4; r++) acc[mt][nt][r] = 0.f;

    load_chunk(0);

    for (int kt = 0; kt < NCHUNK; kt++) {
        mbar_wait((kt & 1) ? mb1 : mb0, (kt >> 1) & 1);
        __syncthreads();
        if (kt + 1 < NCHUNK) load_chunk(kt + 1);

        const uint32_t st = sb + (uint32_t)(kt & 1) * STAGEB;
#pragma unroll
        for (int kk = 0; kk < 8; kk++) {
            uint32_t ah[2][4];
            LDSM_X4_T(ah[0], st + a_off[0] + kk * 8192);
            LDSM_X4_T(ah[1], st + a_off[1] + kk * 8192);
#pragma unroll
            for (int p = 0; p < 4; p++) {
                uint32_t bh[4];
                LDSM_X4_T(bh, st + b_off[p] + kk * 4096);
#pragma unroll
                for (int mt = 0; mt < 2; mt++) {
                    MMA_F16(acc[mt][2 * p],     ah[mt][0], ah[mt][1], ah[mt][2], ah[mt][3], bh[0], bh[1]);
                    MMA_F16(acc[mt][2 * p + 1], ah[mt][0], ah[mt][1], ah[mt][2], ah[mt][3], bh[2], bh[3]);
                }
            }
        }
    }

    // ---- epilogue ----
    const int mrow = lane >> 2;
    const int cpair = (lane & 3) * 2;
    const int which = QKV ? (n0 >> 11) : 0;
    const int nseg = QKV ? (n0 & 2047) : n0;
    const int h = nseg >> 7;
    const float* bp = QKV ? (which == 0 ? b0p : which == 1 ? b1p : b2p) : b0p;
    __half* outh = QKV ? (which == 0 ? g_Qh : which == 1 ? g_Kh : g_Vh) : nullptr;

#pragma unroll
    for (int mt = 0; mt < 2; mt++) {
#pragma unroll
        for (int rr = 0; rr < 2; rr++) {
            const int m = m0 + warp_m + mt * 16 + mrow + rr * 8;
            const int b = m >> 12;
            const int s = m & (Sc - 1);
#pragma unroll
            for (int nt = 0; nt < 8; nt++) {
                const int nl = warp_n + nt * 8 + cpair;
                float v0 = acc[mt][nt][rr * 2 + 0] + bp[nseg + nl];
                float v1 = acc[mt][nt][rr * 2 + 1] + bp[nseg + nl + 1];
                if (QKV) {
                    if (which < 2) {
                        const float cs = cosT[(size_t)s * Dc + nl];
                        const float sn = sinT[(size_t)s * Dc + nl];
                        const float e = v0 * cs - v1 * sn;
                        const float o_ = v1 * cs + v0 * sn;
                        v0 = fmaxf(e, 0.f);
                        v1 = fmaxf(o_, 0.f);
                    }
                    const size_t oi = (((size_t)b * Hc + h) * Sc + s) * Dc + nl;
                    *(uint32_t*)(outh + oi) = pack_h2(v0, v1);
                } else {
                    *(float2*)(dout + (size_t)m * Cc + nseg + nl) = make_float2(v0, v1);
                }
            }
        }
    }
}

// ======================= fp16 HMMA VK (R13 proven, NSPLIT=8) ================
#define VROW 272
#define VK_KOFF (64 * VROW)

__global__ void __launch_bounds__(256) vk_mma()
{
    __shared__ __align__(16) char sm[2 * VK_KOFF];
    const int bh = blockIdx.x;
    const int sp = blockIdx.y;
    const int tid = threadIdx.x;
    const int lane = tid & 31;
    const int wid = tid >> 5;
    const int warp_m = (wid >> 1) * 32;
    const int warp_n = (wid & 1) * 64;
    const uint32_t sb = smem_u32(sm);

    const __half* Vg = g_Vh + (size_t)bh * Sc * Dc;
    const __half* Kg = g_Kh + (size_t)bh * Sc * Dc;

    uint32_t a_off[2];
#pragma unroll
    for (int mt = 0; mt < 2; mt++) {
        const int kIdx = (lane & 7) + ((lane >> 4) << 3);
        const int mOff = ((lane >> 3) & 1) * 8;
        a_off[mt] = (uint32_t)kIdx * VROW + (uint32_t)(warp_m + mt * 16 + mOff) * 2;
    }
    uint32_t b_off[4];
#pragma unroll
    for (int p = 0; p < 4; p++) {
        const int kIdx = (lane & 7) + (((lane >> 3) & 1) << 3);
        const int nOff = (lane >> 4) * 8;
        b_off[p] = VK_KOFF + (uint32_t)kIdx * VROW + (uint32_t)(warp_n + p * 16 + nOff) * 2;
    }

    float acc[2][8][4];
#pragma unroll
    for (int mt = 0; mt < 2; mt++)
#pragma unroll
        for (int nt = 0; nt < 8; nt++)
#pragma unroll
            for (int r = 0; r < 4; r++) acc[mt][nt][r] = 0.f;
    float csum = 0.f;

    const int sbase = sp * (Sc / NSPLIT);
    for (int ch = 0; ch < (Sc / NSPLIT) / 64; ch++) {
        const int s0 = sbase + ch * 64;
        for (int idx = tid; idx < 64 * 16; idx += 256) {
            const int r = idx >> 4, c = idx & 15;
            *(uint4*)(sm + r * VROW + c * 16) =
                *(const uint4*)(Vg + (size_t)(s0 + r) * Dc + c * 8);
            *(uint4*)(sm + VK_KOFF + r * VROW + c * 16) =
                *(const uint4*)(Kg + (size_t)(s0 + r) * Dc + c * 8);
        }
        __syncthreads();

#pragma unroll
        for (int kk = 0; kk < 4; kk++) {
            uint32_t ah[2][4];
            LDSM_X4_T(ah[0], sb + a_off[0] + kk * (16 * VROW));
            LDSM_X4_T(ah[1], sb + a_off[1] + kk * (16 * VROW));
#pragma unroll
            for (int p = 0; p < 4; p++) {
                uint32_t bh[4];
                LDSM_X4_T(bh, sb + b_off[p] + kk * (16 * VROW));
#pragma unroll
                for (int mt = 0; mt < 2; mt++) {
                    MMA_F16(acc[mt][2 * p],     ah[mt][0], ah[mt][1], ah[mt][2], ah[mt][3], bh[0], bh[1]);
                    MMA_F16(acc[mt][2 * p + 1], ah[mt][0], ah[mt][1], ah[mt][2], ah[mt][3], bh[2], bh[3]);
                }
            }
        }
        if (tid < 128) {
            const __half* kc = (const __half*)(sm + VK_KOFF) + tid;
#pragma unroll 16
            for (int r = 0; r < 64; r++)
                csum += __half2float(*(const __half*)((const char*)kc + r * VROW));
        }
        __syncthreads();
    }

    float* P = &g_VKpart[sp][(size_t)bh * 129 * Dc];
    const int mrow = lane >> 2;
    const int cpair = (lane & 3) * 2;
#pragma unroll
    for (int mt = 0; mt < 2; mt++) {
#pragma unroll
        for (int rr = 0; rr < 2; rr++) {
            const int n = warp_m + mt * 16 + mrow + rr * 8;
#pragma unroll
            for (int nt = 0; nt < 8; nt++) {
                const int d = warp_n + nt * 8 + cpair;
                *(float2*)&P[(size_t)n * Dc + d] =
                    make_float2(acc[mt][nt][rr * 2], acc[mt][nt][rr * 2 + 1]);
            }
        }
    }
    if (tid < 128) P[(size_t)128 * Dc + tid] = csum;
}

__global__ void vk_reduce()
{
    const int i = blockIdx.x * 256 + threadIdx.x;
    if (i < Bc * Hc * 129 * Dc / 2) {
        float2 s = make_float2(0.f, 0.f);
#pragma unroll
        for (int p = 0; p < NSPLIT; p++) {
            const float2 v = *(const float2*)&g_VKpart[p][(size_t)i * 2];
            s.x += v.x; s.y += v.y;
        }
        *(uint32_t*)(g_VKh + (size_t)i * 2) = pack_h2(s.x, s.y);
    }
}

// ======================= fp16 HMMA attn; writes ATT_T tiled (unchanged) ======
#define QROW 272
#define SM_VK 34816
#define SM_DEN (34816 + 35088)

__global__ void __launch_bounds__(256) attn_mma()
{
    extern __shared__ __align__(16) char sm[];
    float* den = (float*)(sm + SM_DEN);

    const int bh = blockIdx.x;
    const int b = bh >> 4, h = bh & 15;
    const int s0 = blockIdx.y * 128;
    const int tid = threadIdx.x;
    const int lane = tid & 31;
    const int wid = tid >> 5;
    const int warp_m = (wid >> 1) * 32;
    const int warp_n = (wid & 1) * 64;

    const uint32_t sb = smem_u32(sm);

    const __half* Qg = g_Qh + ((size_t)bh * Sc + s0) * Dc;
    for (int idx = tid; idx < 128 * 16; idx += 256) {
        const int r = idx >> 4, c = idx & 15;
        *(uint4*)(sm + r * QROW + c * 16) = *(const uint4*)(Qg + (size_t)r * Dc + c * 8);
    }
    const __half* VKg = g_VKh + (size_t)bh * 129 * Dc;
    for (int idx = tid; idx < 129 * 16; idx += 256) {
        const int r = idx >> 4, c = idx & 15;
        *(uint4*)(sm + SM_VK + r * QROW + c * 16) = *(const uint4*)(VKg + (size_t)r * Dc + c * 8);
    }
    __syncthreads();

    float acc[2][8][4];
#pragma unroll
    for (int mt = 0; mt < 2; mt++)
#pragma unroll
        for (int nt = 0; nt < 8; nt++)
#pragma unroll
            for (int r = 0; r < 4; r++) acc[mt][nt][r] = 0.f;

    uint32_t a_addr[2];
#pragma unroll
    for (int mt = 0; mt < 2; mt++)
        a_addr[mt] = sb + (warp_m + mt * 16 + (lane & 15)) * QROW + (lane >> 4) * 16;
    uint32_t b_addr[4];
#pragma unroll
    for (int p = 0; p < 4; p++)
        b_addr[p] = sb + SM_VK +
            (warp_n + p * 16 + ((lane >> 4) & 1) * 8 + (lane & 7)) * QROW +
            ((lane >> 3) & 1) * 16;

#pragma unroll
    for (int ks = 0; ks < 8; ks++) {
        uint32_t ah[2][4];
        LDSM_X4(ah[0], a_addr[0] + ks * 32);
        LDSM_X4(ah[1], a_addr[1] + ks * 32);
#pragma unroll
        for (int p = 0; p < 4; p++) {
            uint32_t bhreg[4];
            LDSM_X4(bhreg, b_addr[p] + ks * 32);
#pragma unroll
            for (int mt = 0; mt < 2; mt++) {
                MMA_F16(acc[mt][2 * p],     ah[mt][0], ah[mt][1], ah[mt][2], ah[mt][3], bhreg[0], bhreg[1]);
                MMA_F16(acc[mt][2 * p + 1], ah[mt][0], ah[mt][1], ah[mt][2], ah[mt][3], bhreg[2], bhreg[3]);
            }
        }
    }

    if (tid < 128) {
        const __half2* vrow = (const __half2*)(sm + SM_VK + 128 * QROW);
        const __half2* qrow = (const __half2*)(sm + tid * QROW);
        float d = 0.f;
#pragma unroll 8
        for (int i = 0; i < 64; i++) {
            const float2 v = __half22float2(vrow[i]);
            const float2 q = __half22float2(qrow[i]);
            d = fmaf(v.x, q.x, d);
            d = fmaf(v.y, q.y, d);
        }
        den[tid] = 1.0f / (d + 1e-15f);
    }
    __syncthreads();

    const int mrow = lane >> 2;
    const int cpair = (lane & 3) * 2;
#pragma unroll
    for (int mt = 0; mt < 2; mt++) {
#pragma unroll
        for (int rr = 0; rr < 2; rr++) {
            const int m = warp_m + mt * 16 + mrow + rr * 8;
            const float inv = den[m];
#pragma unroll
            for (int nt = 0; nt < 8; nt++) {
                const int n = warp_n + nt * 8 + cpair;
                *(uint32_t*)(sm + m * QROW + n * 2) =
                    pack_h2(acc[mt][nt][rr * 2] * inv, acc[mt][nt][rr * 2 + 1] * inv);
            }
        }
    }
    __syncthreads();

    const int mbase = b * Sc + s0;
    const int mblk = mbase >> 8;
    const int cb = (mbase & 255) >> 3;
    for (int ci = tid; ci < 128 * 16; ci += 256) {
        const int c_loc = ci >> 4, p = ci & 15;
        const int c = h * 128 + c_loc;
        const int cl = p ^ (c & 7);
        __half v[8];
#pragma unroll
        for (int j = 0; j < 8; j++)
            v[j] = *(__half*)(sm + (cl * 8 + j) * QROW + c_loc * 2);
        __half* o = g_ATT_T + (size_t)mblk * 524288 + (size_t)c * 256 + (cb + p) * 8;
        *(uint4*)o = *(uint4*)v;
    }
}

// ======================= launch =======================
extern "C" void kernel_launch(void* const* d_in, const int* in_sizes, int n_in,
                              void* d_out, int out_size)
{
    (void)in_sizes; (void)n_in; (void)out_size;
    const float* x    = (const float*)d_in[0];
    const float* cosT = (const float*)d_in[1];
    const float* sinT = (const float*)d_in[2];
    const float* Wq   = (const float*)d_in[3];
    const float* bq   = (const float*)d_in[4];
    const float* Wk   = (const float*)d_in[5];
    const float* bk   = (const float*)d_in[6];
    const float* Wv   = (const float*)d_in[7];
    const float* bv   = (const float*)d_in[8];
    const float* Wo   = (const float*)d_in[9];
    const float* bo   = (const float*)d_in[10];
    float* out = (float*)d_out;

    __half *xT, *wT, *attT;
    cudaGetSymbolAddress((void**)&xT, g_XT);
    cudaGetSymbolAddress((void**)&wT, g_WT);
    cudaGetSymbolAddress((void**)&attT, g_ATT_T);

    const size_t WTM = (size_t)16 * 262144;
    // single merged convert launch: x (y<128) + 4 weights (y>=128)
    convert_all<<<dim3(32, 256), 256>>>(x, Wq, Wk, Wv, Wo, xT, wT);

    const int gsm = 2 * STAGEB;   // 196608
    cudaFuncSetAttribute(mma_gemm<0>, cudaFuncAttributeMaxDynamicSharedMemorySize, gsm);
    cudaFuncSetAttribute(mma_gemm<1>, cudaFuncAttributeMaxDynamicSharedMemorySize, gsm);

    // merged QKV: N = 6144, grid (48, 32)
    mma_gemm<1><<<dim3(48, 32), NT, gsm>>>(xT, wT, bq, bk, bv, cosT, sinT, nullptr);

    vk_mma<<<dim3(Bc * Hc, NSPLIT), 256>>>();
    vk_reduce<<<(Bc * Hc * 129 * Dc / 2 + 255) / 256, 256>>>();

    const int asm_ = SM_DEN + 128 * sizeof(float) + 16;   // ~70.4KB
    cudaFuncSetAttribute(attn_mma, cudaFuncAttributeMaxDynamicSharedMemorySize, asm_);
    attn_mma<<<dim3(Bc * Hc, Sc / 128), 256, asm_>>>();

    // O projection
    mma_gemm<0><<<dim3(16, 32), NT, gsm>>>(attT, wT + 3 * WTM, bo, bo, bo,
                                           nullptr, nullptr, out);
}